// round 15
// baseline (speedup 1.0000x reference)
#include <cuda_runtime.h>

#define N_ 20000
#define E_ 100000
#define KF 8
#define FIN 1024
#define FOUT 512
#define KTOT 1120
#define MS 32768

// ---------------- device scratch (no allocations) ----------------
__device__ float               g_f[KF * N_];
__device__ int                 g_par[KF * N_];
__device__ int                 g_hk[KF * N_];
__device__ unsigned long long  g_best[KF * N_];
__device__ unsigned long long  g_feA[KF * E_];
__device__ unsigned long long  g_feB[KF * E_];
__device__ int                 g_fcnt[2][KF];
__device__ unsigned long long  g_mk[KF * MS];
__device__ int                 g_mcnt[KF];
__device__ float               g_D[KF * N_];
__device__ float               g_coord[(size_t)N_ * 96];

// ---------------- packed f32x2 helpers ----------------
#define FMA2(d, a, b) asm("fma.rn.f32x2 %0, %1, %2, %0;" : "+l"(d) : "l"(a), "l"(b))
#define PK2(d, x, y)  asm("mov.b64 %0, {%1, %2};" : "=l"(d) : "f"(x), "f"(y))
#define UPK2(x, y, d) asm("mov.b64 {%0, %1}, %2;" : "=f"(x), "=f"(y) : "l"(d))

// ---------------- init ----------------
__global__ void k_init() {
    int i = blockIdx.x * blockDim.x + threadIdx.x;
    if (i < KF * N_) { g_par[i] = i % N_; g_best[i] = ~0ull; }
    if (i < KF * MS) g_mk[i] = ~0ull;
    if (i < KF)      { g_mcnt[i] = 0; g_fcnt[0][i] = 0; g_fcnt[1][i] = 0; }
}

// ---------------- f_all ----------------
__global__ __launch_bounds__(256) void k_fall(const float* __restrict__ x,
                                              const float* __restrict__ fw,
                                              const float* __restrict__ fb) {
    __shared__ float ws[KF][FIN];
    int tid = threadIdx.x;
    for (int i = tid; i < KF * FIN; i += 256) ws[i >> 10][i & 1023] = fw[i];
    __syncthreads();
    int warp = tid >> 5, lane = tid & 31;
    int row = blockIdx.x * 8 + warp;
    if (row >= N_) return;
    const float4* xr = (const float4*)(x + (size_t)row * FIN);
    float acc[KF];
#pragma unroll
    for (int k = 0; k < KF; k++) acc[k] = 0.f;
    for (int i = lane; i < FIN / 4; i += 32) {
        float4 xv = xr[i];
        int c = i * 4;
#pragma unroll
        for (int k = 0; k < KF; k++)
            acc[k] += xv.x * ws[k][c] + xv.y * ws[k][c + 1] +
                      xv.z * ws[k][c + 2] + xv.w * ws[k][c + 3];
    }
#pragma unroll
    for (int k = 0; k < KF; k++)
#pragma unroll
        for (int o = 16; o; o >>= 1) acc[k] += __shfl_xor_sync(0xFFFFFFFFu, acc[k], o);
    if (lane == 0) {
#pragma unroll
        for (int k = 0; k < KF; k++) g_f[k * N_ + row] = acc[k] + fb[k];
    }
}

// ---------------- Boruvka A: round0 computes keys inline; best atomics + compaction ----------------
__global__ void kA_edge(const int* __restrict__ ei, int r) {
    int p = r & 1;
    int i = blockIdx.x * blockDim.x + threadIdx.x;
    int k = i / E_, j = i - k * E_;
    int lane = threadIdx.x & 31;
    bool keep = false;
    unsigned long long kv = 0;
    int lim = (r == 0) ? E_ : g_fcnt[p][k];
    if (j < lim) {
        int e, u, v;
        if (r == 0) {
            e = j; u = ei[e]; v = ei[E_ + e];
            float key = fmaxf(g_f[k * N_ + u], g_f[k * N_ + v]);
            unsigned b = __float_as_uint(key);
            b = (b & 0x80000000u) ? ~b : (b | 0x80000000u);
            kv = ((unsigned long long)b << 32) | (unsigned)e;
        } else {
            kv = p ? g_feB[i] : g_feA[i];
            e = (int)(unsigned)kv; u = ei[e]; v = ei[E_ + e];
        }
        int cu = g_par[k * N_ + u], cv = g_par[k * N_ + v];
        if (cu != cv) {
            atomicMin(&g_best[k * N_ + cu], kv);
            atomicMin(&g_best[k * N_ + cv], kv);
            keep = true;
        }
    }
    unsigned m = __ballot_sync(0xFFFFFFFFu, keep);
    if (!m) return;
    int leader = __ffs(m) - 1;
    int pos = 0;
    if (lane == leader) pos = atomicAdd(&g_fcnt[p ^ 1][k], __popc(m));
    pos = __shfl_sync(0xFFFFFFFFu, pos, leader);
    if (keep) {
        int my = pos + __popc(m & ((1u << lane) - 1));
        if (p) g_feA[k * E_ + my] = kv; else g_feB[k * E_ + my] = kv;
    }
}

// ---------------- Boruvka B: hook + warp-aggregated MSF append (dead-round exit) ----------------
__global__ void kB_hook(const int* __restrict__ ei, int r) {
    int i = blockIdx.x * blockDim.x + threadIdx.x;
    int k = i / N_, n = i - k * N_;
    if (r > 0 && g_fcnt[r & 1][k] == 0) return;
    int lane = threadIdx.x & 31;
    bool emit = false;
    unsigned long long bb = 0;
    if (g_par[i] == n) {
        bb = g_best[i];
        if (bb == ~0ull) {
            g_hk[i] = -1;
        } else {
            unsigned e = (unsigned)bb;
            int u = ei[e], v = ei[E_ + e];
            int cu = g_par[k * N_ + u], cv = g_par[k * N_ + v];
            int o = (cu == n) ? cv : cu;
            g_hk[i] = o;
            unsigned long long bb2 = g_best[k * N_ + o];
            bool recip = (bb2 == bb);
            emit = (!recip || n < o);
        }
    }
    unsigned m = __ballot_sync(0xFFFFFFFFu, emit);
    if (!m) return;
    int leader = __ffs(m) - 1;
    int pos = 0;
    if (lane == leader) pos = atomicAdd(&g_mcnt[k], __popc(m));
    pos = __shfl_sync(0xFFFFFFFFu, pos, leader);
    if (emit) {
        int my = pos + __popc(m & ((1u << lane) - 1));
        g_mk[(size_t)k * MS + my] = bb;
    }
}

// ---------------- Boruvka C: apply hooks + flatten + reset (dead-round exit) ----------------
__global__ void kC_flat(int r) {
    int p = r & 1;
    int i = blockIdx.x * blockDim.x + threadIdx.x;
    if (i >= KF * N_) return;
    int k = i / N_, n = i - k * N_;
    if (r > 0 && g_fcnt[p][k] == 0) return;
    int kb = k * N_;
    int x = n;
    for (;;) {
        int pp = g_par[kb + x];
        if (pp != x) { x = pp; continue; }
        int o = g_hk[kb + x];
        if (o < 0) break;
        if (g_hk[kb + o] == x && x < o) break;
        x = o;
    }
    g_par[i] = x;
    g_best[i] = ~0ull;
    if (n == 0) g_fcnt[p][k] = 0;
}

// ---------------- bitonic sort ----------------
__global__ __launch_bounds__(1024) void k_sloc() {
    __shared__ unsigned long long s[2048];
    unsigned blk = blockIdx.x;
    size_t base = (size_t)blk * 2048;
    unsigned lbase = (blk % (MS / 2048)) * 2048;
    s[threadIdx.x] = g_mk[base + threadIdx.x];
    s[threadIdx.x + 1024] = g_mk[base + threadIdx.x + 1024];
    __syncthreads();
    for (unsigned k2 = 2; k2 <= 2048; k2 <<= 1) {
        for (unsigned j = k2 >> 1; j > 0; j >>= 1) {
            unsigned t = threadIdx.x;
            unsigned i = 2 * t - (t & (j - 1));
            bool up = (((lbase + i) & k2) == 0);
            unsigned long long a = s[i], b = s[i + j];
            if (up ? (a > b) : (a < b)) { s[i] = b; s[i + j] = a; }
            __syncthreads();
        }
    }
    g_mk[base + threadIdx.x] = s[threadIdx.x];
    g_mk[base + threadIdx.x + 1024] = s[threadIdx.x + 1024];
}

__global__ void k_sglob(unsigned K2, unsigned j) {
    unsigned gid = blockIdx.x * blockDim.x + threadIdx.x;
    if (gid >= KF * (MS / 2)) return;
    unsigned filt = gid / (MS / 2), t = gid % (MS / 2);
    unsigned i = 2 * t - (t & (j - 1));
    unsigned l = i + j;
    unsigned long long* g = g_mk + (size_t)filt * MS;
    bool up = ((i & K2) == 0);
    unsigned long long a = g[i], b = g[l];
    if (up ? (a > b) : (a < b)) { g[i] = b; g[l] = a; }
}

__global__ __launch_bounds__(1024) void k_smerge(unsigned K2) {
    __shared__ unsigned long long s[2048];
    unsigned blk = blockIdx.x;
    size_t base = (size_t)blk * 2048;
    unsigned lbase = (blk % (MS / 2048)) * 2048;
    s[threadIdx.x] = g_mk[base + threadIdx.x];
    s[threadIdx.x + 1024] = g_mk[base + threadIdx.x + 1024];
    __syncthreads();
    for (unsigned j = 1024; j > 0; j >>= 1) {
        unsigned t = threadIdx.x;
        unsigned i = 2 * t - (t & (j - 1));
        bool up = (((lbase + i) & K2) == 0);
        unsigned long long a = s[i], b = s[i + j];
        if (up ? (a > b) : (a < b)) { s[i] = b; s[i + j] = a; }
        __syncthreads();
    }
    g_mk[base + threadIdx.x] = s[threadIdx.x];
    g_mk[base + threadIdx.x + 1024] = s[threadIdx.x + 1024];
}

// ---------------- elder-rule UF: hybrid conflict-gated commit ----------------
// Prefind as R10. Then a dependency-free conflict scan; conflict-free batches
// commit all 32 merges in parallel (disjoint roots => equals sequential order);
// conflicted batches run the exact R10 register-mirrored serial loop.
__global__ __launch_bounds__(32) void k_uf(const int* __restrict__ ei) {
    extern __shared__ char dyn[];
    float* sf = (float*)dyn;
    unsigned short* spar = (unsigned short*)(dyn + 80000);
    int k = blockIdx.x, lane = threadIdx.x;
    const float* f = g_f + (size_t)k * N_;
    float* D = g_D + (size_t)k * N_;
    {
        const float4* f4 = (const float4*)f;
        float4* D4 = (float4*)D;
        float4* sf4 = (float4*)sf;
        for (int i = lane; i < N_ / 4; i += 32) { float4 v = f4[i]; sf4[i] = v; D4[i] = v; }
        ushort2* sp2 = (ushort2*)spar;
        for (int i = lane; i < N_ / 2; i += 32)
            sp2[i] = make_ushort2((unsigned short)(2 * i), (unsigned short)(2 * i + 1));
    }
    __syncwarp();
    int m = g_mcnt[k];
    const unsigned long long* mk = g_mk + (size_t)k * MS;
    for (int base = 0; base < m; base += 32) {
        int i = base + lane;
        bool valid = (i < m);
        // per-lane distinct dummies: never match anything (incl. other invalid lanes)
        int ru = -(2 * lane + 2), rv = -(2 * lane + 3);
        float fu = 0.f, fv = 0.f, kf = 0.f;
        if (valid) {
            unsigned long long kv = mk[i];
            unsigned e = (unsigned)kv;
            unsigned ob = (unsigned)(kv >> 32);
            unsigned fb2 = (ob & 0x80000000u) ? (ob & 0x7FFFFFFFu) : ~ob;
            kf = __uint_as_float(fb2);
            int u = ei[e], v = ei[E_ + e];
            int x = u;
            for (;;) { int p = spar[x]; if (p == x) break; int g2 = spar[p]; spar[x] = (unsigned short)g2; x = g2; }
            ru = x; fu = sf[x];
            x = v;
            for (;;) { int p = spar[x]; if (p == x) break; int g2 = spar[p]; spar[x] = (unsigned short)g2; x = g2; }
            rv = x; fv = sf[x];
        }
        __syncwarp();
        // dependency-free conflict scan: lane i conflicts iff it shares a root
        // with any earlier lane j < i (all shfls independent -> pipelined)
        bool conflict = false;
#pragma unroll
        for (int j = 0; j < 31; j++) {
            int oru = __shfl_sync(0xFFFFFFFFu, ru, j);
            int orv = __shfl_sync(0xFFFFFFFFu, rv, j);
            if (j < lane && (oru == ru || oru == rv || orv == ru || orv == rv)) conflict = true;
        }
        if (!__any_sync(0xFFFFFFFFu, conflict)) {
            // parallel commit: pairwise-disjoint roots -> commutes, equals Kruskal order
            if (valid && ru != rv) {
                int older   = (fu <= fv) ? ru : rv;
                int younger = ru + rv - older;
                spar[younger] = (unsigned short)older;
                D[younger] = kf;
            }
        } else {
            // exact R10 serial register-mirrored loop
            int lim = min(32, m - base);
            for (int t = 0; t < lim; t++) {
                int   bru = __shfl_sync(0xFFFFFFFFu, ru, t);
                int   brv = __shfl_sync(0xFFFFFFFFu, rv, t);
                float bfu = __shfl_sync(0xFFFFFFFFu, fu, t);
                float bfv = __shfl_sync(0xFFFFFFFFu, fv, t);
                float bkf = __shfl_sync(0xFFFFFFFFu, kf, t);
                if (bru != brv) {
                    int older   = (bfu <= bfv) ? bru : brv;
                    int younger = bru + brv - older;
                    float folder = (bfu <= bfv) ? bfu : bfv;
                    if (lane == (t & 31)) {
                        spar[younger] = (unsigned short)older;
                        D[younger] = bkf;
                    }
                    if (ru == younger) { ru = older; fu = folder; }
                    if (rv == younger) { rv = older; fv = folder; }
                }
            }
        }
        __syncwarp();
    }
}

// ---------------- coordinate activations ----------------
__global__ void k_act(const float* __restrict__ tri_t, const float* __restrict__ mu,
                      const float* __restrict__ sig, const float* __restrict__ lw,
                      const float* __restrict__ rc, const float* __restrict__ rr) {
    int i = blockIdx.x * blockDim.x + threadIdx.x;
    if (i >= N_ * KF) return;
    int v = i / KF, k = i - v * KF;
    float b = g_f[k * N_ + v], d = g_D[k * N_ + v];
    float s = sig[0];
    float inv = 1.f / (2.f * s * s);
    float r = fabsf(rr[0]);
    float o[12];
#pragma unroll
    for (int j = 0; j < 3; j++) o[j] = fmaxf(0.f, d - fabsf(tri_t[j] - b));
#pragma unroll
    for (int j = 0; j < 3; j++) {
        float dx = b - mu[2 * j], dy = d - mu[2 * j + 1];
        o[3 + j] = expf(-(dx * dx + dy * dy) * inv);
    }
#pragma unroll
    for (int j = 0; j < 3; j++) o[6 + j] = b * lw[2 * j] + d * lw[2 * j + 1];
#pragma unroll
    for (int j = 0; j < 3; j++) {
        float q = fabsf(b - rc[2 * j]) + fabsf(d - rc[2 * j + 1]);
        o[9 + j] = 1.f / (1.f + q) - 1.f / (1.f + fabsf(r - q));
    }
    float* dst = g_coord + (size_t)v * 96 + k * 12;
#pragma unroll
    for (int j = 0; j < 12; j++) dst[j] = o[j];
}

// ---------------- GEMM part 1: out = x @ Wx^T + bias ----------------
__global__ __launch_bounds__(256, 2) void k_gemm_x(const float* __restrict__ x,
                                                   const float* __restrict__ W,
                                                   const float* __restrict__ bias,
                                                   float* __restrict__ out) {
    __shared__ float As[16][136];
    __shared__ float Ws[16][136];
    int tid = threadIdx.x;
    int tx = tid & 15, ty = tid >> 4;
    int row0 = blockIdx.x * 128;
    int col0 = blockIdx.y * 128;
    unsigned long long acc[4][8];
#pragma unroll
    for (int p2 = 0; p2 < 4; p2++)
#pragma unroll
        for (int j = 0; j < 8; j++) acc[p2][j] = 0ull;

    for (int kt = 0; kt < 64; kt++) {
        int k0 = kt * 16;
#pragma unroll
        for (int l = 0; l < 2; l++) {
            int idx = tid + l * 256;
            int r = idx >> 2, c4 = idx & 3;
            int grow = row0 + r;
            float4 vv = make_float4(0.f, 0.f, 0.f, 0.f);
            if (grow < N_) vv = *(const float4*)(x + (size_t)grow * FIN + (k0 + c4 * 4));
            As[c4 * 4 + 0][r] = vv.x; As[c4 * 4 + 1][r] = vv.y;
            As[c4 * 4 + 2][r] = vv.z; As[c4 * 4 + 3][r] = vv.w;
        }
#pragma unroll
        for (int l = 0; l < 2; l++) {
            int idx = tid + l * 256;
            int r = idx >> 2, c4 = idx & 3;
            float4 vv = *(const float4*)(W + (size_t)(col0 + r) * KTOT + (k0 + c4 * 4));
            Ws[c4 * 4 + 0][r] = vv.x; Ws[c4 * 4 + 1][r] = vv.y;
            Ws[c4 * 4 + 2][r] = vv.z; Ws[c4 * 4 + 3][r] = vv.w;
        }
        __syncthreads();
#pragma unroll
        for (int kk = 0; kk < 16; kk++) {
            const unsigned long long* a8 = (const unsigned long long*)(&As[kk][ty * 8]);
            unsigned long long ap0 = a8[0], ap1 = a8[1], ap2 = a8[2], ap3 = a8[3];
            float4 w0 = *(const float4*)&Ws[kk][tx * 8];
            float4 w1 = *(const float4*)&Ws[kk][tx * 8 + 4];
            unsigned long long wp[8];
            PK2(wp[0], w0.x, w0.x); PK2(wp[1], w0.y, w0.y);
            PK2(wp[2], w0.z, w0.z); PK2(wp[3], w0.w, w0.w);
            PK2(wp[4], w1.x, w1.x); PK2(wp[5], w1.y, w1.y);
            PK2(wp[6], w1.z, w1.z); PK2(wp[7], w1.w, w1.w);
#pragma unroll
            for (int j = 0; j < 8; j++) {
                FMA2(acc[0][j], ap0, wp[j]);
                FMA2(acc[1][j], ap1, wp[j]);
                FMA2(acc[2][j], ap2, wp[j]);
                FMA2(acc[3][j], ap3, wp[j]);
            }
        }
        __syncthreads();
    }

    float bs[8];
#pragma unroll
    for (int j = 0; j < 8; j++) bs[j] = bias[col0 + tx * 8 + j];
#pragma unroll
    for (int p2 = 0; p2 < 4; p2++) {
        float lo[8], hi[8];
#pragma unroll
        for (int j = 0; j < 8; j++) { UPK2(lo[j], hi[j], acc[p2][j]); }
        int r0 = row0 + ty * 8 + p2 * 2;
        if (r0 < N_) {
            float* o0 = out + (size_t)r0 * FOUT + col0 + tx * 8;
            *(float4*)o0 = make_float4(lo[0] + bs[0], lo[1] + bs[1], lo[2] + bs[2], lo[3] + bs[3]);
            *(float4*)(o0 + 4) = make_float4(lo[4] + bs[4], lo[5] + bs[5], lo[6] + bs[6], lo[7] + bs[7]);
        }
        if (r0 + 1 < N_) {
            float* o1 = out + (size_t)(r0 + 1) * FOUT + col0 + tx * 8;
            *(float4*)o1 = make_float4(hi[0] + bs[0], hi[1] + bs[1], hi[2] + bs[2], hi[3] + bs[3]);
            *(float4*)(o1 + 4) = make_float4(hi[4] + bs[4], hi[5] + bs[5], hi[6] + bs[6], hi[7] + bs[7]);
        }
    }
}

// ---------------- GEMM part 2: out += coord @ Wc^T ----------------
__global__ __launch_bounds__(256, 2) void k_gemm_c(const float* __restrict__ W,
                                                   float* __restrict__ out) {
    __shared__ float As[16][136];
    __shared__ float Ws[16][136];
    int tid = threadIdx.x;
    int tx = tid & 15, ty = tid >> 4;
    int row0 = blockIdx.x * 128;
    int col0 = blockIdx.y * 128;
    unsigned long long acc[4][8];
#pragma unroll
    for (int p2 = 0; p2 < 4; p2++)
#pragma unroll
        for (int j = 0; j < 8; j++) acc[p2][j] = 0ull;

    for (int kt = 0; kt < 6; kt++) {
        int k0 = kt * 16;
#pragma unroll
        for (int l = 0; l < 2; l++) {
            int idx = tid + l * 256;
            int r = idx >> 2, c4 = idx & 3;
            int grow = row0 + r;
            float4 vv = make_float4(0.f, 0.f, 0.f, 0.f);
            if (grow < N_) vv = *(const float4*)(g_coord + (size_t)grow * 96 + (k0 + c4 * 4));
            As[c4 * 4 + 0][r] = vv.x; As[c4 * 4 + 1][r] = vv.y;
            As[c4 * 4 + 2][r] = vv.z; As[c4 * 4 + 3][r] = vv.w;
        }
#pragma unroll
        for (int l = 0; l < 2; l++) {
            int idx = tid + l * 256;
            int r = idx >> 2, c4 = idx & 3;
            float4 vv = *(const float4*)(W + (size_t)(col0 + r) * KTOT + (1024 + k0 + c4 * 4));
            Ws[c4 * 4 + 0][r] = vv.x; Ws[c4 * 4 + 1][r] = vv.y;
            Ws[c4 * 4 + 2][r] = vv.z; Ws[c4 * 4 + 3][r] = vv.w;
        }
        __syncthreads();
#pragma unroll
        for (int kk = 0; kk < 16; kk++) {
            const unsigned long long* a8 = (const unsigned long long*)(&As[kk][ty * 8]);
            unsigned long long ap0 = a8[0], ap1 = a8[1], ap2 = a8[2], ap3 = a8[3];
            float4 w0 = *(const float4*)&Ws[kk][tx * 8];
            float4 w1 = *(const float4*)&Ws[kk][tx * 8 + 4];
            unsigned long long wp[8];
            PK2(wp[0], w0.x, w0.x); PK2(wp[1], w0.y, w0.y);
            PK2(wp[2], w0.z, w0.z); PK2(wp[3], w0.w, w0.w);
            PK2(wp[4], w1.x, w1.x); PK2(wp[5], w1.y, w1.y);
            PK2(wp[6], w1.z, w1.z); PK2(wp[7], w1.w, w1.w);
#pragma unroll
            for (int j = 0; j < 8; j++) {
                FMA2(acc[0][j], ap0, wp[j]);
                FMA2(acc[1][j], ap1, wp[j]);
                FMA2(acc[2][j], ap2, wp[j]);
                FMA2(acc[3][j], ap3, wp[j]);
            }
        }
        __syncthreads();
    }

#pragma unroll
    for (int p2 = 0; p2 < 4; p2++) {
        float lo[8], hi[8];
#pragma unroll
        for (int j = 0; j < 8; j++) { UPK2(lo[j], hi[j], acc[p2][j]); }
        int r0 = row0 + ty * 8 + p2 * 2;
        if (r0 < N_) {
            float* o0 = out + (size_t)r0 * FOUT + col0 + tx * 8;
            float4 a0 = *(float4*)o0, a1 = *(float4*)(o0 + 4);
            a0.x += lo[0]; a0.y += lo[1]; a0.z += lo[2]; a0.w += lo[3];
            a1.x += lo[4]; a1.y += lo[5]; a1.z += lo[6]; a1.w += lo[7];
            *(float4*)o0 = a0; *(float4*)(o0 + 4) = a1;
        }
        if (r0 + 1 < N_) {
            float* o1 = out + (size_t)(r0 + 1) * FOUT + col0 + tx * 8;
            float4 a0 = *(float4*)o1, a1 = *(float4*)(o1 + 4);
            a0.x += hi[0]; a0.y += hi[1]; a0.z += hi[2]; a0.w += hi[3];
            a1.x += hi[4]; a1.y += hi[5]; a1.z += hi[6]; a1.w += hi[7];
            *(float4*)o1 = a0; *(float4*)(o1 + 4) = a1;
        }
    }
}

// ---------------- launcher: topology on HIGH-priority stream; x-GEMM on default ----------------
extern "C" void kernel_launch(void* const* d_in, const int* in_sizes, int n_in,
                              void* d_out, int out_size) {
    const float* x   = (const float*)d_in[0];
    const int*   ei  = (const int*)d_in[1];
    const float* fw  = (const float*)d_in[2];
    const float* fb  = (const float*)d_in[3];
    const float* tri = (const float*)d_in[4];
    const float* mu  = (const float*)d_in[5];
    const float* sig = (const float*)d_in[6];
    const float* lw  = (const float*)d_in[7];
    const float* rc  = (const float*)d_in[8];
    const float* rr  = (const float*)d_in[9];
    const float* W   = (const float*)d_in[10];
    const float* ob  = (const float*)d_in[11];
    float* out = (float*)d_out;

    int loPri = 0, hiPri = 0;
    cudaDeviceGetStreamPriorityRange(&loPri, &hiPri);
    cudaStream_t s1;
    cudaStreamCreateWithPriority(&s1, cudaStreamNonBlocking, hiPri);
    cudaEvent_t evRoot, evT;
    cudaEventCreateWithFlags(&evRoot, cudaEventDisableTiming);
    cudaEventCreateWithFlags(&evT, cudaEventDisableTiming);

    dim3 gg((N_ + 127) / 128, FOUT / 128);

    cudaEventRecord(evRoot, 0);
    cudaStreamWaitEvent(s1, evRoot, 0);

    // x-GEMM on default (lowest-priority) stream
    k_gemm_x<<<gg, 256>>>(x, W, ob, out);

    // topology pipeline on s1
    k_init<<<(KF * MS + 255) / 256, 256, 0, s1>>>();
    k_fall<<<(N_ + 7) / 8, 256, 0, s1>>>(x, fw, fb);

    for (int r = 0; r < 15; r++) {
        kA_edge<<<KF * E_ / 256, 256, 0, s1>>>(ei, r);
        kB_hook<<<KF * N_ / 256, 256, 0, s1>>>(ei, r);
        kC_flat<<<(KF * N_ + 255) / 256, 256, 0, s1>>>(r);
    }

    k_sloc<<<KF * (MS / 2048), 1024, 0, s1>>>();
    for (unsigned K2 = 4096; K2 <= MS; K2 <<= 1) {
        for (unsigned j = K2 >> 1; j >= 2048; j >>= 1)
            k_sglob<<<(KF * (MS / 2) + 255) / 256, 256, 0, s1>>>(K2, j);
        k_smerge<<<KF * (MS / 2048), 1024, 0, s1>>>(K2);
    }

    cudaFuncSetAttribute(k_uf, cudaFuncAttributeMaxDynamicSharedMemorySize, 122880);
    k_uf<<<KF, 32, 120000, s1>>>(ei);
    k_act<<<(N_ * KF + 255) / 256, 256, 0, s1>>>(tri, mu, sig, lw, rc, rr);
    cudaEventRecord(evT, s1);

    cudaStreamWaitEvent(0, evT, 0);
    k_gemm_c<<<gg, 256>>>(W, out);
}

// round 16
// speedup vs baseline: 1.0454x; 1.0454x over previous
#include <cuda_runtime.h>

#define N_ 20000
#define E_ 100000
#define KF 8
#define FIN 1024
#define FOUT 512
#define KTOT 1120
#define MS 32768

// ---------------- device scratch (no allocations) ----------------
__device__ float               g_f[KF * N_];
__device__ int                 g_par[KF * N_];
__device__ int                 g_hk[KF * N_];
__device__ unsigned long long  g_best[KF * N_];
__device__ unsigned long long  g_feA[KF * E_];
__device__ unsigned long long  g_feB[KF * E_];
__device__ int                 g_fcnt[2][KF];
__device__ unsigned long long  g_mk[KF * MS];
__device__ int                 g_mcnt[KF];
__device__ float               g_D[KF * N_];
__device__ float               g_coord[(size_t)N_ * 96];

// ---------------- packed f32x2 helpers ----------------
#define FMA2(d, a, b) asm("fma.rn.f32x2 %0, %1, %2, %0;" : "+l"(d) : "l"(a), "l"(b))
#define PK2(d, x, y)  asm("mov.b64 %0, {%1, %2};" : "=l"(d) : "f"(x), "f"(y))
#define UPK2(x, y, d) asm("mov.b64 {%0, %1}, %2;" : "=f"(x), "=f"(y) : "l"(d))

// ---------------- init ----------------
__global__ void k_init() {
    int i = blockIdx.x * blockDim.x + threadIdx.x;
    if (i < KF * N_) { g_par[i] = i % N_; g_best[i] = ~0ull; }
    if (i < KF * MS) g_mk[i] = ~0ull;
    if (i < KF)      { g_mcnt[i] = 0; g_fcnt[0][i] = 0; g_fcnt[1][i] = 0; }
}

// ---------------- f_all ----------------
__global__ __launch_bounds__(256) void k_fall(const float* __restrict__ x,
                                              const float* __restrict__ fw,
                                              const float* __restrict__ fb) {
    __shared__ float ws[KF][FIN];
    int tid = threadIdx.x;
    for (int i = tid; i < KF * FIN; i += 256) ws[i >> 10][i & 1023] = fw[i];
    __syncthreads();
    int warp = tid >> 5, lane = tid & 31;
    int row = blockIdx.x * 8 + warp;
    if (row >= N_) return;
    const float4* xr = (const float4*)(x + (size_t)row * FIN);
    float acc[KF];
#pragma unroll
    for (int k = 0; k < KF; k++) acc[k] = 0.f;
    for (int i = lane; i < FIN / 4; i += 32) {
        float4 xv = xr[i];
        int c = i * 4;
#pragma unroll
        for (int k = 0; k < KF; k++)
            acc[k] += xv.x * ws[k][c] + xv.y * ws[k][c + 1] +
                      xv.z * ws[k][c + 2] + xv.w * ws[k][c + 3];
    }
#pragma unroll
    for (int k = 0; k < KF; k++)
#pragma unroll
        for (int o = 16; o; o >>= 1) acc[k] += __shfl_xor_sync(0xFFFFFFFFu, acc[k], o);
    if (lane == 0) {
#pragma unroll
        for (int k = 0; k < KF; k++) g_f[k * N_ + row] = acc[k] + fb[k];
    }
}

// ---------------- Boruvka A: round0 computes keys inline; best atomics + compaction ----------------
__global__ void kA_edge(const int* __restrict__ ei, int r) {
    int p = r & 1;
    int i = blockIdx.x * blockDim.x + threadIdx.x;
    int k = i / E_, j = i - k * E_;
    int lane = threadIdx.x & 31;
    bool keep = false;
    unsigned long long kv = 0;
    int lim = (r == 0) ? E_ : g_fcnt[p][k];
    if (j < lim) {
        int e, u, v;
        if (r == 0) {
            e = j; u = ei[e]; v = ei[E_ + e];
            float key = fmaxf(g_f[k * N_ + u], g_f[k * N_ + v]);
            unsigned b = __float_as_uint(key);
            b = (b & 0x80000000u) ? ~b : (b | 0x80000000u);
            kv = ((unsigned long long)b << 32) | (unsigned)e;
        } else {
            kv = p ? g_feB[i] : g_feA[i];
            e = (int)(unsigned)kv; u = ei[e]; v = ei[E_ + e];
        }
        int cu = g_par[k * N_ + u], cv = g_par[k * N_ + v];
        if (cu != cv) {
            atomicMin(&g_best[k * N_ + cu], kv);
            atomicMin(&g_best[k * N_ + cv], kv);
            keep = true;
        }
    }
    unsigned m = __ballot_sync(0xFFFFFFFFu, keep);
    if (!m) return;
    int leader = __ffs(m) - 1;
    int pos = 0;
    if (lane == leader) pos = atomicAdd(&g_fcnt[p ^ 1][k], __popc(m));
    pos = __shfl_sync(0xFFFFFFFFu, pos, leader);
    if (keep) {
        int my = pos + __popc(m & ((1u << lane) - 1));
        if (p) g_feA[k * E_ + my] = kv; else g_feB[k * E_ + my] = kv;
    }
}

// ---------------- Boruvka B: hook + warp-aggregated MSF append (dead-round exit) ----------------
__global__ void kB_hook(const int* __restrict__ ei, int r) {
    int i = blockIdx.x * blockDim.x + threadIdx.x;
    int k = i / N_, n = i - k * N_;
    if (r > 0 && g_fcnt[r & 1][k] == 0) return;
    int lane = threadIdx.x & 31;
    bool emit = false;
    unsigned long long bb = 0;
    if (g_par[i] == n) {
        bb = g_best[i];
        if (bb == ~0ull) {
            g_hk[i] = -1;
        } else {
            unsigned e = (unsigned)bb;
            int u = ei[e], v = ei[E_ + e];
            int cu = g_par[k * N_ + u], cv = g_par[k * N_ + v];
            int o = (cu == n) ? cv : cu;
            g_hk[i] = o;
            unsigned long long bb2 = g_best[k * N_ + o];
            bool recip = (bb2 == bb);
            emit = (!recip || n < o);
        }
    }
    unsigned m = __ballot_sync(0xFFFFFFFFu, emit);
    if (!m) return;
    int leader = __ffs(m) - 1;
    int pos = 0;
    if (lane == leader) pos = atomicAdd(&g_mcnt[k], __popc(m));
    pos = __shfl_sync(0xFFFFFFFFu, pos, leader);
    if (emit) {
        int my = pos + __popc(m & ((1u << lane) - 1));
        g_mk[(size_t)k * MS + my] = bb;
    }
}

// ---------------- Boruvka C: apply hooks + flatten + reset (dead-round exit) ----------------
__global__ void kC_flat(int r) {
    int p = r & 1;
    int i = blockIdx.x * blockDim.x + threadIdx.x;
    if (i >= KF * N_) return;
    int k = i / N_, n = i - k * N_;
    if (r > 0 && g_fcnt[p][k] == 0) return;
    int kb = k * N_;
    int x = n;
    for (;;) {
        int pp = g_par[kb + x];
        if (pp != x) { x = pp; continue; }
        int o = g_hk[kb + x];
        if (o < 0) break;
        if (g_hk[kb + o] == x && x < o) break;
        x = o;
    }
    g_par[i] = x;
    g_best[i] = ~0ull;
    if (n == 0) g_fcnt[p][k] = 0;
}

// ---------------- sort: 16384-element in-smem chunks (3 launches total) ----------------
// k_sloc16: each block sorts one 16384-chunk in 128KB dynamic smem.
// Direction uses the global index (lbase + i), so chunk 0 ends ascending and
// chunk 1 descending — completing all bitonic stages k2 <= 16384 exactly as
// the reference network would.
__global__ __launch_bounds__(1024) void k_sloc16() {
    extern __shared__ unsigned long long s16[];
    unsigned blk = blockIdx.x;
    size_t base = (size_t)blk * 16384;
    unsigned lbase = (blk & 1) * 16384;      // chunk index within filtration
    for (int i = threadIdx.x; i < 16384; i += 1024) s16[i] = g_mk[base + i];
    __syncthreads();
    for (unsigned k2 = 2; k2 <= 16384; k2 <<= 1) {
        for (unsigned j = k2 >> 1; j > 0; j >>= 1) {
            for (int t = threadIdx.x; t < 8192; t += 1024) {
                unsigned i = 2 * (unsigned)t - ((unsigned)t & (j - 1));
                bool up = (((lbase + i) & k2) == 0);
                unsigned long long a = s16[i], b = s16[i + j];
                if (up ? (a > b) : (a < b)) { s16[i] = b; s16[i + j] = a; }
            }
            __syncthreads();
        }
    }
    for (int i = threadIdx.x; i < 16384; i += 1024) g_mk[base + i] = s16[i];
}

__global__ void k_sglob(unsigned K2, unsigned j) {
    unsigned gid = blockIdx.x * blockDim.x + threadIdx.x;
    if (gid >= KF * (MS / 2)) return;
    unsigned filt = gid / (MS / 2), t = gid % (MS / 2);
    unsigned i = 2 * t - (t & (j - 1));
    unsigned l = i + j;
    unsigned long long* g = g_mk + (size_t)filt * MS;
    bool up = ((i & K2) == 0);
    unsigned long long a = g[i], b = g[l];
    if (up ? (a > b) : (a < b)) { g[i] = b; g[l] = a; }
}

// k_smerge16: final K2=MS merge inside each 16384-chunk (j = 8192..1).
// For K2 = MS = 32768 every in-range global index has (idx & K2) == 0 -> ascending.
__global__ __launch_bounds__(1024) void k_smerge16() {
    extern __shared__ unsigned long long s16[];
    unsigned blk = blockIdx.x;
    size_t base = (size_t)blk * 16384;
    for (int i = threadIdx.x; i < 16384; i += 1024) s16[i] = g_mk[base + i];
    __syncthreads();
    for (unsigned j = 8192; j > 0; j >>= 1) {
        for (int t = threadIdx.x; t < 8192; t += 1024) {
            unsigned i = 2 * (unsigned)t - ((unsigned)t & (j - 1));
            unsigned long long a = s16[i], b = s16[i + j];
            if (a > b) { s16[i] = b; s16[i + j] = a; }
        }
        __syncthreads();
    }
    for (int i = threadIdx.x; i < 16384; i += 1024) g_mk[base + i] = s16[i];
}

// ---------------- elder-rule UF: warp-synchronous register-mirrored commit (R10/R14 winner) ----------------
__global__ __launch_bounds__(32) void k_uf(const int* __restrict__ ei) {
    extern __shared__ char dyn[];
    float* sf = (float*)dyn;
    unsigned short* spar = (unsigned short*)(dyn + 80000);
    int k = blockIdx.x, lane = threadIdx.x;
    const float* f = g_f + (size_t)k * N_;
    float* D = g_D + (size_t)k * N_;
    {
        const float4* f4 = (const float4*)f;
        float4* D4 = (float4*)D;
        float4* sf4 = (float4*)sf;
        for (int i = lane; i < N_ / 4; i += 32) { float4 v = f4[i]; sf4[i] = v; D4[i] = v; }
        ushort2* sp2 = (ushort2*)spar;
        for (int i = lane; i < N_ / 2; i += 32)
            sp2[i] = make_ushort2((unsigned short)(2 * i), (unsigned short)(2 * i + 1));
    }
    __syncwarp();
    int m = g_mcnt[k];
    const unsigned long long* mk = g_mk + (size_t)k * MS;
    for (int base = 0; base < m; base += 32) {
        int i = base + lane;
        bool valid = (i < m);
        int ru = -1, rv = -2;
        float fu = 0.f, fv = 0.f, kf = 0.f;
        if (valid) {
            unsigned long long kv = mk[i];
            unsigned e = (unsigned)kv;
            unsigned ob = (unsigned)(kv >> 32);
            unsigned fb2 = (ob & 0x80000000u) ? (ob & 0x7FFFFFFFu) : ~ob;
            kf = __uint_as_float(fb2);
            int u = ei[e], v = ei[E_ + e];
            int x = u;
            for (;;) { int p = spar[x]; if (p == x) break; int g2 = spar[p]; spar[x] = (unsigned short)g2; x = g2; }
            ru = x; fu = sf[x];
            x = v;
            for (;;) { int p = spar[x]; if (p == x) break; int g2 = spar[p]; spar[x] = (unsigned short)g2; x = g2; }
            rv = x; fv = sf[x];
        }
        __syncwarp();
        int lim = min(32, m - base);
        for (int t = 0; t < lim; t++) {
            int   bru = __shfl_sync(0xFFFFFFFFu, ru, t);
            int   brv = __shfl_sync(0xFFFFFFFFu, rv, t);
            float bfu = __shfl_sync(0xFFFFFFFFu, fu, t);
            float bfv = __shfl_sync(0xFFFFFFFFu, fv, t);
            float bkf = __shfl_sync(0xFFFFFFFFu, kf, t);
            if (bru != brv) {
                int older   = (bfu <= bfv) ? bru : brv;
                int younger = bru + brv - older;
                float folder = (bfu <= bfv) ? bfu : bfv;
                if (lane == (t & 31)) {
                    spar[younger] = (unsigned short)older;
                    D[younger] = bkf;
                }
                if (ru == younger) { ru = older; fu = folder; }
                if (rv == younger) { rv = older; fv = folder; }
            }
        }
        __syncwarp();
    }
}

// ---------------- coordinate activations ----------------
__global__ void k_act(const float* __restrict__ tri_t, const float* __restrict__ mu,
                      const float* __restrict__ sig, const float* __restrict__ lw,
                      const float* __restrict__ rc, const float* __restrict__ rr) {
    int i = blockIdx.x * blockDim.x + threadIdx.x;
    if (i >= N_ * KF) return;
    int v = i / KF, k = i - v * KF;
    float b = g_f[k * N_ + v], d = g_D[k * N_ + v];
    float s = sig[0];
    float inv = 1.f / (2.f * s * s);
    float r = fabsf(rr[0]);
    float o[12];
#pragma unroll
    for (int j = 0; j < 3; j++) o[j] = fmaxf(0.f, d - fabsf(tri_t[j] - b));
#pragma unroll
    for (int j = 0; j < 3; j++) {
        float dx = b - mu[2 * j], dy = d - mu[2 * j + 1];
        o[3 + j] = expf(-(dx * dx + dy * dy) * inv);
    }
#pragma unroll
    for (int j = 0; j < 3; j++) o[6 + j] = b * lw[2 * j] + d * lw[2 * j + 1];
#pragma unroll
    for (int j = 0; j < 3; j++) {
        float q = fabsf(b - rc[2 * j]) + fabsf(d - rc[2 * j + 1]);
        o[9 + j] = 1.f / (1.f + q) - 1.f / (1.f + fabsf(r - q));
    }
    float* dst = g_coord + (size_t)v * 96 + k * 12;
#pragma unroll
    for (int j = 0; j < 12; j++) dst[j] = o[j];
}

// ---------------- GEMM part 1: out = x @ Wx^T + bias ----------------
__global__ __launch_bounds__(256, 2) void k_gemm_x(const float* __restrict__ x,
                                                   const float* __restrict__ W,
                                                   const float* __restrict__ bias,
                                                   float* __restrict__ out) {
    __shared__ float As[16][136];
    __shared__ float Ws[16][136];
    int tid = threadIdx.x;
    int tx = tid & 15, ty = tid >> 4;
    int row0 = blockIdx.x * 128;
    int col0 = blockIdx.y * 128;
    unsigned long long acc[4][8];
#pragma unroll
    for (int p2 = 0; p2 < 4; p2++)
#pragma unroll
        for (int j = 0; j < 8; j++) acc[p2][j] = 0ull;

    for (int kt = 0; kt < 64; kt++) {
        int k0 = kt * 16;
#pragma unroll
        for (int l = 0; l < 2; l++) {
            int idx = tid + l * 256;
            int r = idx >> 2, c4 = idx & 3;
            int grow = row0 + r;
            float4 vv = make_float4(0.f, 0.f, 0.f, 0.f);
            if (grow < N_) vv = *(const float4*)(x + (size_t)grow * FIN + (k0 + c4 * 4));
            As[c4 * 4 + 0][r] = vv.x; As[c4 * 4 + 1][r] = vv.y;
            As[c4 * 4 + 2][r] = vv.z; As[c4 * 4 + 3][r] = vv.w;
        }
#pragma unroll
        for (int l = 0; l < 2; l++) {
            int idx = tid + l * 256;
            int r = idx >> 2, c4 = idx & 3;
            float4 vv = *(const float4*)(W + (size_t)(col0 + r) * KTOT + (k0 + c4 * 4));
            Ws[c4 * 4 + 0][r] = vv.x; Ws[c4 * 4 + 1][r] = vv.y;
            Ws[c4 * 4 + 2][r] = vv.z; Ws[c4 * 4 + 3][r] = vv.w;
        }
        __syncthreads();
#pragma unroll
        for (int kk = 0; kk < 16; kk++) {
            const unsigned long long* a8 = (const unsigned long long*)(&As[kk][ty * 8]);
            unsigned long long ap0 = a8[0], ap1 = a8[1], ap2 = a8[2], ap3 = a8[3];
            float4 w0 = *(const float4*)&Ws[kk][tx * 8];
            float4 w1 = *(const float4*)&Ws[kk][tx * 8 + 4];
            unsigned long long wp[8];
            PK2(wp[0], w0.x, w0.x); PK2(wp[1], w0.y, w0.y);
            PK2(wp[2], w0.z, w0.z); PK2(wp[3], w0.w, w0.w);
            PK2(wp[4], w1.x, w1.x); PK2(wp[5], w1.y, w1.y);
            PK2(wp[6], w1.z, w1.z); PK2(wp[7], w1.w, w1.w);
#pragma unroll
            for (int j = 0; j < 8; j++) {
                FMA2(acc[0][j], ap0, wp[j]);
                FMA2(acc[1][j], ap1, wp[j]);
                FMA2(acc[2][j], ap2, wp[j]);
                FMA2(acc[3][j], ap3, wp[j]);
            }
        }
        __syncthreads();
    }

    float bs[8];
#pragma unroll
    for (int j = 0; j < 8; j++) bs[j] = bias[col0 + tx * 8 + j];
#pragma unroll
    for (int p2 = 0; p2 < 4; p2++) {
        float lo[8], hi[8];
#pragma unroll
        for (int j = 0; j < 8; j++) { UPK2(lo[j], hi[j], acc[p2][j]); }
        int r0 = row0 + ty * 8 + p2 * 2;
        if (r0 < N_) {
            float* o0 = out + (size_t)r0 * FOUT + col0 + tx * 8;
            *(float4*)o0 = make_float4(lo[0] + bs[0], lo[1] + bs[1], lo[2] + bs[2], lo[3] + bs[3]);
            *(float4*)(o0 + 4) = make_float4(lo[4] + bs[4], lo[5] + bs[5], lo[6] + bs[6], lo[7] + bs[7]);
        }
        if (r0 + 1 < N_) {
            float* o1 = out + (size_t)(r0 + 1) * FOUT + col0 + tx * 8;
            *(float4*)o1 = make_float4(hi[0] + bs[0], hi[1] + bs[1], hi[2] + bs[2], hi[3] + bs[3]);
            *(float4*)(o1 + 4) = make_float4(hi[4] + bs[4], hi[5] + bs[5], hi[6] + bs[6], hi[7] + bs[7]);
        }
    }
}

// ---------------- GEMM part 2: out += coord @ Wc^T ----------------
__global__ __launch_bounds__(256, 2) void k_gemm_c(const float* __restrict__ W,
                                                   float* __restrict__ out) {
    __shared__ float As[16][136];
    __shared__ float Ws[16][136];
    int tid = threadIdx.x;
    int tx = tid & 15, ty = tid >> 4;
    int row0 = blockIdx.x * 128;
    int col0 = blockIdx.y * 128;
    unsigned long long acc[4][8];
#pragma unroll
    for (int p2 = 0; p2 < 4; p2++)
#pragma unroll
        for (int j = 0; j < 8; j++) acc[p2][j] = 0ull;

    for (int kt = 0; kt < 6; kt++) {
        int k0 = kt * 16;
#pragma unroll
        for (int l = 0; l < 2; l++) {
            int idx = tid + l * 256;
            int r = idx >> 2, c4 = idx & 3;
            int grow = row0 + r;
            float4 vv = make_float4(0.f, 0.f, 0.f, 0.f);
            if (grow < N_) vv = *(const float4*)(g_coord + (size_t)grow * 96 + (k0 + c4 * 4));
            As[c4 * 4 + 0][r] = vv.x; As[c4 * 4 + 1][r] = vv.y;
            As[c4 * 4 + 2][r] = vv.z; As[c4 * 4 + 3][r] = vv.w;
        }
#pragma unroll
        for (int l = 0; l < 2; l++) {
            int idx = tid + l * 256;
            int r = idx >> 2, c4 = idx & 3;
            float4 vv = *(const float4*)(W + (size_t)(col0 + r) * KTOT + (1024 + k0 + c4 * 4));
            Ws[c4 * 4 + 0][r] = vv.x; Ws[c4 * 4 + 1][r] = vv.y;
            Ws[c4 * 4 + 2][r] = vv.z; Ws[c4 * 4 + 3][r] = vv.w;
        }
        __syncthreads();
#pragma unroll
        for (int kk = 0; kk < 16; kk++) {
            const unsigned long long* a8 = (const unsigned long long*)(&As[kk][ty * 8]);
            unsigned long long ap0 = a8[0], ap1 = a8[1], ap2 = a8[2], ap3 = a8[3];
            float4 w0 = *(const float4*)&Ws[kk][tx * 8];
            float4 w1 = *(const float4*)&Ws[kk][tx * 8 + 4];
            unsigned long long wp[8];
            PK2(wp[0], w0.x, w0.x); PK2(wp[1], w0.y, w0.y);
            PK2(wp[2], w0.z, w0.z); PK2(wp[3], w0.w, w0.w);
            PK2(wp[4], w1.x, w1.x); PK2(wp[5], w1.y, w1.y);
            PK2(wp[6], w1.z, w1.z); PK2(wp[7], w1.w, w1.w);
#pragma unroll
            for (int j = 0; j < 8; j++) {
                FMA2(acc[0][j], ap0, wp[j]);
                FMA2(acc[1][j], ap1, wp[j]);
                FMA2(acc[2][j], ap2, wp[j]);
                FMA2(acc[3][j], ap3, wp[j]);
            }
        }
        __syncthreads();
    }

#pragma unroll
    for (int p2 = 0; p2 < 4; p2++) {
        float lo[8], hi[8];
#pragma unroll
        for (int j = 0; j < 8; j++) { UPK2(lo[j], hi[j], acc[p2][j]); }
        int r0 = row0 + ty * 8 + p2 * 2;
        if (r0 < N_) {
            float* o0 = out + (size_t)r0 * FOUT + col0 + tx * 8;
            float4 a0 = *(float4*)o0, a1 = *(float4*)(o0 + 4);
            a0.x += lo[0]; a0.y += lo[1]; a0.z += lo[2]; a0.w += lo[3];
            a1.x += lo[4]; a1.y += lo[5]; a1.z += lo[6]; a1.w += lo[7];
            *(float4*)o0 = a0; *(float4*)(o0 + 4) = a1;
        }
        if (r0 + 1 < N_) {
            float* o1 = out + (size_t)(r0 + 1) * FOUT + col0 + tx * 8;
            float4 a0 = *(float4*)o1, a1 = *(float4*)(o1 + 4);
            a0.x += hi[0]; a0.y += hi[1]; a0.z += hi[2]; a0.w += hi[3];
            a1.x += hi[4]; a1.y += hi[5]; a1.z += hi[6]; a1.w += hi[7];
            *(float4*)o1 = a0; *(float4*)(o1 + 4) = a1;
        }
    }
}

// ---------------- launcher: topology on HIGH-priority stream; x-GEMM on default ----------------
extern "C" void kernel_launch(void* const* d_in, const int* in_sizes, int n_in,
                              void* d_out, int out_size) {
    const float* x   = (const float*)d_in[0];
    const int*   ei  = (const int*)d_in[1];
    const float* fw  = (const float*)d_in[2];
    const float* fb  = (const float*)d_in[3];
    const float* tri = (const float*)d_in[4];
    const float* mu  = (const float*)d_in[5];
    const float* sig = (const float*)d_in[6];
    const float* lw  = (const float*)d_in[7];
    const float* rc  = (const float*)d_in[8];
    const float* rr  = (const float*)d_in[9];
    const float* W   = (const float*)d_in[10];
    const float* ob  = (const float*)d_in[11];
    float* out = (float*)d_out;

    int loPri = 0, hiPri = 0;
    cudaDeviceGetStreamPriorityRange(&loPri, &hiPri);
    cudaStream_t s1;
    cudaStreamCreateWithPriority(&s1, cudaStreamNonBlocking, hiPri);
    cudaEvent_t evRoot, evT;
    cudaEventCreateWithFlags(&evRoot, cudaEventDisableTiming);
    cudaEventCreateWithFlags(&evT, cudaEventDisableTiming);

    dim3 gg((N_ + 127) / 128, FOUT / 128);

    cudaEventRecord(evRoot, 0);
    cudaStreamWaitEvent(s1, evRoot, 0);

    // x-GEMM on default (lowest-priority) stream
    k_gemm_x<<<gg, 256>>>(x, W, ob, out);

    // topology pipeline on s1
    k_init<<<(KF * MS + 255) / 256, 256, 0, s1>>>();
    k_fall<<<(N_ + 7) / 8, 256, 0, s1>>>(x, fw, fb);

    for (int r = 0; r < 15; r++) {
        kA_edge<<<KF * E_ / 256, 256, 0, s1>>>(ei, r);
        kB_hook<<<KF * N_ / 256, 256, 0, s1>>>(ei, r);
        kC_flat<<<(KF * N_ + 255) / 256, 256, 0, s1>>>(r);
    }

    // 3-launch sort: in-smem 16384-chunk local sorts, one global pass, in-smem final merge
    cudaFuncSetAttribute(k_sloc16, cudaFuncAttributeMaxDynamicSharedMemorySize, 131072);
    cudaFuncSetAttribute(k_smerge16, cudaFuncAttributeMaxDynamicSharedMemorySize, 131072);
    k_sloc16<<<KF * 2, 1024, 131072, s1>>>();
    k_sglob<<<(KF * (MS / 2) + 255) / 256, 256, 0, s1>>>(32768u, 16384u);
    k_smerge16<<<KF * 2, 1024, 131072, s1>>>();

    cudaFuncSetAttribute(k_uf, cudaFuncAttributeMaxDynamicSharedMemorySize, 122880);
    k_uf<<<KF, 32, 120000, s1>>>(ei);
    k_act<<<(N_ * KF + 255) / 256, 256, 0, s1>>>(tri, mu, sig, lw, rc, rr);
    cudaEventRecord(evT, s1);

    cudaStreamWaitEvent(0, evT, 0);
    k_gemm_c<<<gg, 256>>>(W, out);
}

// round 17
// speedup vs baseline: 1.1924x; 1.1406x over previous
#include <cuda_runtime.h>

#define N_ 20000
#define E_ 100000
#define KF 8
#define FIN 1024
#define FOUT 512
#define KTOT 1120
#define MS 32768

// ---------------- device scratch (no allocations) ----------------
__device__ float               g_f[KF * N_];
__device__ int                 g_par[KF * N_];
__device__ int                 g_hk[KF * N_];
__device__ unsigned long long  g_best[KF * N_];
__device__ unsigned long long  g_feA[KF * E_];
__device__ unsigned long long  g_feB[KF * E_];
__device__ int                 g_fcnt[2][KF];
__device__ unsigned long long  g_mk[KF * MS];
__device__ int                 g_mcnt[KF];
__device__ float               g_D[KF * N_];
__device__ float               g_coord[(size_t)N_ * 96];

// ---------------- packed f32x2 helpers ----------------
#define FMA2(d, a, b) asm("fma.rn.f32x2 %0, %1, %2, %0;" : "+l"(d) : "l"(a), "l"(b))
#define PK2(d, x, y)  asm("mov.b64 %0, {%1, %2};" : "=l"(d) : "f"(x), "f"(y))
#define UPK2(x, y, d) asm("mov.b64 {%0, %1}, %2;" : "=f"(x), "=f"(y) : "l"(d))

__device__ __forceinline__ unsigned f2tf32(float f) {
    unsigned r;
    asm("cvt.rna.tf32.f32 %0, %1;" : "=r"(r) : "f"(f));
    return r;
}

// ---------------- init ----------------
__global__ void k_init() {
    int i = blockIdx.x * blockDim.x + threadIdx.x;
    if (i < KF * N_) { g_par[i] = i % N_; g_best[i] = ~0ull; }
    if (i < KF * MS) g_mk[i] = ~0ull;
    if (i < KF)      { g_mcnt[i] = 0; g_fcnt[0][i] = 0; g_fcnt[1][i] = 0; }
}

// ---------------- f_all ----------------
__global__ __launch_bounds__(256) void k_fall(const float* __restrict__ x,
                                              const float* __restrict__ fw,
                                              const float* __restrict__ fb) {
    __shared__ float ws[KF][FIN];
    int tid = threadIdx.x;
    for (int i = tid; i < KF * FIN; i += 256) ws[i >> 10][i & 1023] = fw[i];
    __syncthreads();
    int warp = tid >> 5, lane = tid & 31;
    int row = blockIdx.x * 8 + warp;
    if (row >= N_) return;
    const float4* xr = (const float4*)(x + (size_t)row * FIN);
    float acc[KF];
#pragma unroll
    for (int k = 0; k < KF; k++) acc[k] = 0.f;
    for (int i = lane; i < FIN / 4; i += 32) {
        float4 xv = xr[i];
        int c = i * 4;
#pragma unroll
        for (int k = 0; k < KF; k++)
            acc[k] += xv.x * ws[k][c] + xv.y * ws[k][c + 1] +
                      xv.z * ws[k][c + 2] + xv.w * ws[k][c + 3];
    }
#pragma unroll
    for (int k = 0; k < KF; k++)
#pragma unroll
        for (int o = 16; o; o >>= 1) acc[k] += __shfl_xor_sync(0xFFFFFFFFu, acc[k], o);
    if (lane == 0) {
#pragma unroll
        for (int k = 0; k < KF; k++) g_f[k * N_ + row] = acc[k] + fb[k];
    }
}

// ---------------- Boruvka A ----------------
__global__ void kA_edge(const int* __restrict__ ei, int r) {
    int p = r & 1;
    int i = blockIdx.x * blockDim.x + threadIdx.x;
    int k = i / E_, j = i - k * E_;
    int lane = threadIdx.x & 31;
    bool keep = false;
    unsigned long long kv = 0;
    int lim = (r == 0) ? E_ : g_fcnt[p][k];
    if (j < lim) {
        int e, u, v;
        if (r == 0) {
            e = j; u = ei[e]; v = ei[E_ + e];
            float key = fmaxf(g_f[k * N_ + u], g_f[k * N_ + v]);
            unsigned b = __float_as_uint(key);
            b = (b & 0x80000000u) ? ~b : (b | 0x80000000u);
            kv = ((unsigned long long)b << 32) | (unsigned)e;
        } else {
            kv = p ? g_feB[i] : g_feA[i];
            e = (int)(unsigned)kv; u = ei[e]; v = ei[E_ + e];
        }
        int cu = g_par[k * N_ + u], cv = g_par[k * N_ + v];
        if (cu != cv) {
            atomicMin(&g_best[k * N_ + cu], kv);
            atomicMin(&g_best[k * N_ + cv], kv);
            keep = true;
        }
    }
    unsigned m = __ballot_sync(0xFFFFFFFFu, keep);
    if (!m) return;
    int leader = __ffs(m) - 1;
    int pos = 0;
    if (lane == leader) pos = atomicAdd(&g_fcnt[p ^ 1][k], __popc(m));
    pos = __shfl_sync(0xFFFFFFFFu, pos, leader);
    if (keep) {
        int my = pos + __popc(m & ((1u << lane) - 1));
        if (p) g_feA[k * E_ + my] = kv; else g_feB[k * E_ + my] = kv;
    }
}

// ---------------- Boruvka B ----------------
__global__ void kB_hook(const int* __restrict__ ei, int r) {
    int i = blockIdx.x * blockDim.x + threadIdx.x;
    int k = i / N_, n = i - k * N_;
    if (r > 0 && g_fcnt[r & 1][k] == 0) return;
    int lane = threadIdx.x & 31;
    bool emit = false;
    unsigned long long bb = 0;
    if (g_par[i] == n) {
        bb = g_best[i];
        if (bb == ~0ull) {
            g_hk[i] = -1;
        } else {
            unsigned e = (unsigned)bb;
            int u = ei[e], v = ei[E_ + e];
            int cu = g_par[k * N_ + u], cv = g_par[k * N_ + v];
            int o = (cu == n) ? cv : cu;
            g_hk[i] = o;
            unsigned long long bb2 = g_best[k * N_ + o];
            bool recip = (bb2 == bb);
            emit = (!recip || n < o);
        }
    }
    unsigned m = __ballot_sync(0xFFFFFFFFu, emit);
    if (!m) return;
    int leader = __ffs(m) - 1;
    int pos = 0;
    if (lane == leader) pos = atomicAdd(&g_mcnt[k], __popc(m));
    pos = __shfl_sync(0xFFFFFFFFu, pos, leader);
    if (emit) {
        int my = pos + __popc(m & ((1u << lane) - 1));
        g_mk[(size_t)k * MS + my] = bb;
    }
}

// ---------------- Boruvka C ----------------
__global__ void kC_flat(int r) {
    int p = r & 1;
    int i = blockIdx.x * blockDim.x + threadIdx.x;
    if (i >= KF * N_) return;
    int k = i / N_, n = i - k * N_;
    if (r > 0 && g_fcnt[p][k] == 0) return;
    int kb = k * N_;
    int x = n;
    for (;;) {
        int pp = g_par[kb + x];
        if (pp != x) { x = pp; continue; }
        int o = g_hk[kb + x];
        if (o < 0) break;
        if (g_hk[kb + o] == x && x < o) break;
        x = o;
    }
    g_par[i] = x;
    g_best[i] = ~0ull;
    if (n == 0) g_fcnt[p][k] = 0;
}

// ---------------- bitonic sort (R14 15-launch version) ----------------
__global__ __launch_bounds__(1024) void k_sloc() {
    __shared__ unsigned long long s[2048];
    unsigned blk = blockIdx.x;
    size_t base = (size_t)blk * 2048;
    unsigned lbase = (blk % (MS / 2048)) * 2048;
    s[threadIdx.x] = g_mk[base + threadIdx.x];
    s[threadIdx.x + 1024] = g_mk[base + threadIdx.x + 1024];
    __syncthreads();
    for (unsigned k2 = 2; k2 <= 2048; k2 <<= 1) {
        for (unsigned j = k2 >> 1; j > 0; j >>= 1) {
            unsigned t = threadIdx.x;
            unsigned i = 2 * t - (t & (j - 1));
            bool up = (((lbase + i) & k2) == 0);
            unsigned long long a = s[i], b = s[i + j];
            if (up ? (a > b) : (a < b)) { s[i] = b; s[i + j] = a; }
            __syncthreads();
        }
    }
    g_mk[base + threadIdx.x] = s[threadIdx.x];
    g_mk[base + threadIdx.x + 1024] = s[threadIdx.x + 1024];
}

__global__ void k_sglob(unsigned K2, unsigned j) {
    unsigned gid = blockIdx.x * blockDim.x + threadIdx.x;
    if (gid >= KF * (MS / 2)) return;
    unsigned filt = gid / (MS / 2), t = gid % (MS / 2);
    unsigned i = 2 * t - (t & (j - 1));
    unsigned l = i + j;
    unsigned long long* g = g_mk + (size_t)filt * MS;
    bool up = ((i & K2) == 0);
    unsigned long long a = g[i], b = g[l];
    if (up ? (a > b) : (a < b)) { g[i] = b; g[l] = a; }
}

__global__ __launch_bounds__(1024) void k_smerge(unsigned K2) {
    __shared__ unsigned long long s[2048];
    unsigned blk = blockIdx.x;
    size_t base = (size_t)blk * 2048;
    unsigned lbase = (blk % (MS / 2048)) * 2048;
    s[threadIdx.x] = g_mk[base + threadIdx.x];
    s[threadIdx.x + 1024] = g_mk[base + threadIdx.x + 1024];
    __syncthreads();
    for (unsigned j = 1024; j > 0; j >>= 1) {
        unsigned t = threadIdx.x;
        unsigned i = 2 * t - (t & (j - 1));
        bool up = (((lbase + i) & K2) == 0);
        unsigned long long a = s[i], b = s[i + j];
        if (up ? (a > b) : (a < b)) { s[i] = b; s[i + j] = a; }
        __syncthreads();
    }
    g_mk[base + threadIdx.x] = s[threadIdx.x];
    g_mk[base + threadIdx.x + 1024] = s[threadIdx.x + 1024];
}

// ---------------- elder-rule UF: warp-synchronous register-mirrored commit (R10/R14 winner) ----------------
__global__ __launch_bounds__(32) void k_uf(const int* __restrict__ ei) {
    extern __shared__ char dyn[];
    float* sf = (float*)dyn;
    unsigned short* spar = (unsigned short*)(dyn + 80000);
    int k = blockIdx.x, lane = threadIdx.x;
    const float* f = g_f + (size_t)k * N_;
    float* D = g_D + (size_t)k * N_;
    {
        const float4* f4 = (const float4*)f;
        float4* D4 = (float4*)D;
        float4* sf4 = (float4*)sf;
        for (int i = lane; i < N_ / 4; i += 32) { float4 v = f4[i]; sf4[i] = v; D4[i] = v; }
        ushort2* sp2 = (ushort2*)spar;
        for (int i = lane; i < N_ / 2; i += 32)
            sp2[i] = make_ushort2((unsigned short)(2 * i), (unsigned short)(2 * i + 1));
    }
    __syncwarp();
    int m = g_mcnt[k];
    const unsigned long long* mk = g_mk + (size_t)k * MS;
    for (int base = 0; base < m; base += 32) {
        int i = base + lane;
        bool valid = (i < m);
        int ru = -1, rv = -2;
        float fu = 0.f, fv = 0.f, kf = 0.f;
        if (valid) {
            unsigned long long kv = mk[i];
            unsigned e = (unsigned)kv;
            unsigned ob = (unsigned)(kv >> 32);
            unsigned fb2 = (ob & 0x80000000u) ? (ob & 0x7FFFFFFFu) : ~ob;
            kf = __uint_as_float(fb2);
            int u = ei[e], v = ei[E_ + e];
            int x = u;
            for (;;) { int p = spar[x]; if (p == x) break; int g2 = spar[p]; spar[x] = (unsigned short)g2; x = g2; }
            ru = x; fu = sf[x];
            x = v;
            for (;;) { int p = spar[x]; if (p == x) break; int g2 = spar[p]; spar[x] = (unsigned short)g2; x = g2; }
            rv = x; fv = sf[x];
        }
        __syncwarp();
        int lim = min(32, m - base);
        for (int t = 0; t < lim; t++) {
            int   bru = __shfl_sync(0xFFFFFFFFu, ru, t);
            int   brv = __shfl_sync(0xFFFFFFFFu, rv, t);
            float bfu = __shfl_sync(0xFFFFFFFFu, fu, t);
            float bfv = __shfl_sync(0xFFFFFFFFu, fv, t);
            float bkf = __shfl_sync(0xFFFFFFFFu, kf, t);
            if (bru != brv) {
                int older   = (bfu <= bfv) ? bru : brv;
                int younger = bru + brv - older;
                float folder = (bfu <= bfv) ? bfu : bfv;
                if (lane == (t & 31)) {
                    spar[younger] = (unsigned short)older;
                    D[younger] = bkf;
                }
                if (ru == younger) { ru = older; fu = folder; }
                if (rv == younger) { rv = older; fv = folder; }
            }
        }
        __syncwarp();
    }
}

// ---------------- coordinate activations ----------------
__global__ void k_act(const float* __restrict__ tri_t, const float* __restrict__ mu,
                      const float* __restrict__ sig, const float* __restrict__ lw,
                      const float* __restrict__ rc, const float* __restrict__ rr) {
    int i = blockIdx.x * blockDim.x + threadIdx.x;
    if (i >= N_ * KF) return;
    int v = i / KF, k = i - v * KF;
    float b = g_f[k * N_ + v], d = g_D[k * N_ + v];
    float s = sig[0];
    float inv = 1.f / (2.f * s * s);
    float r = fabsf(rr[0]);
    float o[12];
#pragma unroll
    for (int j = 0; j < 3; j++) o[j] = fmaxf(0.f, d - fabsf(tri_t[j] - b));
#pragma unroll
    for (int j = 0; j < 3; j++) {
        float dx = b - mu[2 * j], dy = d - mu[2 * j + 1];
        o[3 + j] = expf(-(dx * dx + dy * dy) * inv);
    }
#pragma unroll
    for (int j = 0; j < 3; j++) o[6 + j] = b * lw[2 * j] + d * lw[2 * j + 1];
#pragma unroll
    for (int j = 0; j < 3; j++) {
        float q = fabsf(b - rc[2 * j]) + fabsf(d - rc[2 * j + 1]);
        o[9 + j] = 1.f / (1.f + q) - 1.f / (1.f + fabsf(r - q));
    }
    float* dst = g_coord + (size_t)v * 96 + k * 12;
#pragma unroll
    for (int j = 0; j < 12; j++) dst[j] = o[j];
}

// ---------------- GEMM part 1 (TENSOR CORES, tf32): out = x @ Wx^T + bias ----------------
// Block 128m x 64n, 8 warps as 4x2, warp tile 32x32 (2 m-frags x 4 n-frags),
// mma.sync.m16n8k8.tf32. Smem [k][m]/[k][n] with stride 136/72 (8 mod 32) ->
// conflict-free fragment gathers. RNA tf32 rounding on smem store.
__global__ __launch_bounds__(256, 2) void k_gemm_x(const float* __restrict__ x,
                                                   const float* __restrict__ W,
                                                   const float* __restrict__ bias,
                                                   float* __restrict__ out) {
    __shared__ unsigned As[16][136];
    __shared__ unsigned Bs[16][72];
    int tid = threadIdx.x;
    int warp = tid >> 5, lane = tid & 31;
    int gid = lane >> 2, tig = lane & 3;
    int warpM = warp >> 1, warpN = warp & 1;
    int row0 = blockIdx.x * 128;
    int col0 = blockIdx.y * 64;
    float acc[2][4][4];
#pragma unroll
    for (int a = 0; a < 2; a++)
#pragma unroll
        for (int b = 0; b < 4; b++)
#pragma unroll
            for (int c = 0; c < 4; c++) acc[a][b][c] = 0.f;

    for (int kt = 0; kt < 64; kt++) {
        int k0 = kt * 16;
#pragma unroll
        for (int l = 0; l < 2; l++) {
            int idx = tid + l * 256;
            int r = idx >> 2, c4 = idx & 3;
            int grow = row0 + r;
            float4 vv = make_float4(0.f, 0.f, 0.f, 0.f);
            if (grow < N_) vv = *(const float4*)(x + (size_t)grow * FIN + (k0 + c4 * 4));
            As[c4 * 4 + 0][r] = f2tf32(vv.x);
            As[c4 * 4 + 1][r] = f2tf32(vv.y);
            As[c4 * 4 + 2][r] = f2tf32(vv.z);
            As[c4 * 4 + 3][r] = f2tf32(vv.w);
        }
        {
            int r = tid >> 2, c4 = tid & 3;
            float4 vv = *(const float4*)(W + (size_t)(col0 + r) * KTOT + (k0 + c4 * 4));
            Bs[c4 * 4 + 0][r] = f2tf32(vv.x);
            Bs[c4 * 4 + 1][r] = f2tf32(vv.y);
            Bs[c4 * 4 + 2][r] = f2tf32(vv.z);
            Bs[c4 * 4 + 3][r] = f2tf32(vv.w);
        }
        __syncthreads();
#pragma unroll
        for (int kk = 0; kk < 2; kk++) {
            int kb = kk * 8;
            unsigned af[2][4], bf[4][2];
#pragma unroll
            for (int mf = 0; mf < 2; mf++) {
                int rb = warpM * 32 + mf * 16;
                af[mf][0] = As[kb + tig][rb + gid];
                af[mf][1] = As[kb + tig][rb + gid + 8];
                af[mf][2] = As[kb + tig + 4][rb + gid];
                af[mf][3] = As[kb + tig + 4][rb + gid + 8];
            }
#pragma unroll
            for (int nf = 0; nf < 4; nf++) {
                int nb = warpN * 32 + nf * 8;
                bf[nf][0] = Bs[kb + tig][nb + gid];
                bf[nf][1] = Bs[kb + tig + 4][nb + gid];
            }
#pragma unroll
            for (int mf = 0; mf < 2; mf++)
#pragma unroll
                for (int nf = 0; nf < 4; nf++) {
                    asm volatile(
                        "mma.sync.aligned.m16n8k8.row.col.f32.tf32.tf32.f32 "
                        "{%0,%1,%2,%3}, {%4,%5,%6,%7}, {%8,%9}, {%0,%1,%2,%3};"
                        : "+f"(acc[mf][nf][0]), "+f"(acc[mf][nf][1]),
                          "+f"(acc[mf][nf][2]), "+f"(acc[mf][nf][3])
                        : "r"(af[mf][0]), "r"(af[mf][1]), "r"(af[mf][2]), "r"(af[mf][3]),
                          "r"(bf[nf][0]), "r"(bf[nf][1]));
                }
        }
        __syncthreads();
    }

#pragma unroll
    for (int mf = 0; mf < 2; mf++)
#pragma unroll
        for (int nf = 0; nf < 4; nf++) {
            int col = col0 + warpN * 32 + nf * 8 + 2 * tig;
            float b0v = bias[col], b1v = bias[col + 1];
            int r1 = row0 + warpM * 32 + mf * 16 + gid;
            if (r1 < N_) {
                *(float2*)(out + (size_t)r1 * FOUT + col) =
                    make_float2(acc[mf][nf][0] + b0v, acc[mf][nf][1] + b1v);
            }
            int r2 = r1 + 8;
            if (r2 < N_) {
                *(float2*)(out + (size_t)r2 * FOUT + col) =
                    make_float2(acc[mf][nf][2] + b0v, acc[mf][nf][3] + b1v);
            }
        }
}

// ---------------- GEMM part 2 (fp32 f32x2): out += coord @ Wc^T ----------------
__global__ __launch_bounds__(256, 2) void k_gemm_c(const float* __restrict__ W,
                                                   float* __restrict__ out) {
    __shared__ float As[16][136];
    __shared__ float Ws[16][136];
    int tid = threadIdx.x;
    int tx = tid & 15, ty = tid >> 4;
    int row0 = blockIdx.x * 128;
    int col0 = blockIdx.y * 128;
    unsigned long long acc[4][8];
#pragma unroll
    for (int p2 = 0; p2 < 4; p2++)
#pragma unroll
        for (int j = 0; j < 8; j++) acc[p2][j] = 0ull;

    for (int kt = 0; kt < 6; kt++) {
        int k0 = kt * 16;
#pragma unroll
        for (int l = 0; l < 2; l++) {
            int idx = tid + l * 256;
            int r = idx >> 2, c4 = idx & 3;
            int grow = row0 + r;
            float4 vv = make_float4(0.f, 0.f, 0.f, 0.f);
            if (grow < N_) vv = *(const float4*)(g_coord + (size_t)grow * 96 + (k0 + c4 * 4));
            As[c4 * 4 + 0][r] = vv.x; As[c4 * 4 + 1][r] = vv.y;
            As[c4 * 4 + 2][r] = vv.z; As[c4 * 4 + 3][r] = vv.w;
        }
#pragma unroll
        for (int l = 0; l < 2; l++) {
            int idx = tid + l * 256;
            int r = idx >> 2, c4 = idx & 3;
            float4 vv = *(const float4*)(W + (size_t)(col0 + r) * KTOT + (1024 + k0 + c4 * 4));
            Ws[c4 * 4 + 0][r] = vv.x; Ws[c4 * 4 + 1][r] = vv.y;
            Ws[c4 * 4 + 2][r] = vv.z; Ws[c4 * 4 + 3][r] = vv.w;
        }
        __syncthreads();
#pragma unroll
        for (int kk = 0; kk < 16; kk++) {
            const unsigned long long* a8 = (const unsigned long long*)(&As[kk][ty * 8]);
            unsigned long long ap0 = a8[0], ap1 = a8[1], ap2 = a8[2], ap3 = a8[3];
            float4 w0 = *(const float4*)&Ws[kk][tx * 8];
            float4 w1 = *(const float4*)&Ws[kk][tx * 8 + 4];
            unsigned long long wp[8];
            PK2(wp[0], w0.x, w0.x); PK2(wp[1], w0.y, w0.y);
            PK2(wp[2], w0.z, w0.z); PK2(wp[3], w0.w, w0.w);
            PK2(wp[4], w1.x, w1.x); PK2(wp[5], w1.y, w1.y);
            PK2(wp[6], w1.z, w1.z); PK2(wp[7], w1.w, w1.w);
#pragma unroll
            for (int j = 0; j < 8; j++) {
                FMA2(acc[0][j], ap0, wp[j]);
                FMA2(acc[1][j], ap1, wp[j]);
                FMA2(acc[2][j], ap2, wp[j]);
                FMA2(acc[3][j], ap3, wp[j]);
            }
        }
        __syncthreads();
    }

#pragma unroll
    for (int p2 = 0; p2 < 4; p2++) {
        float lo[8], hi[8];
#pragma unroll
        for (int j = 0; j < 8; j++) { UPK2(lo[j], hi[j], acc[p2][j]); }
        int r0 = row0 + ty * 8 + p2 * 2;
        if (r0 < N_) {
            float* o0 = out + (size_t)r0 * FOUT + col0 + tx * 8;
            float4 a0 = *(float4*)o0, a1 = *(float4*)(o0 + 4);
            a0.x += lo[0]; a0.y += lo[1]; a0.z += lo[2]; a0.w += lo[3];
            a1.x += lo[4]; a1.y += lo[5]; a1.z += lo[6]; a1.w += lo[7];
            *(float4*)o0 = a0; *(float4*)(o0 + 4) = a1;
        }
        if (r0 + 1 < N_) {
            float* o1 = out + (size_t)(r0 + 1) * FOUT + col0 + tx * 8;
            float4 a0 = *(float4*)o1, a1 = *(float4*)(o1 + 4);
            a0.x += hi[0]; a0.y += hi[1]; a0.z += hi[2]; a0.w += hi[3];
            a1.x += hi[4]; a1.y += hi[5]; a1.z += hi[6]; a1.w += hi[7];
            *(float4*)o1 = a0; *(float4*)(o1 + 4) = a1;
        }
    }
}

// ---------------- launcher (R14 structure: topo on high-priority stream) ----------------
extern "C" void kernel_launch(void* const* d_in, const int* in_sizes, int n_in,
                              void* d_out, int out_size) {
    const float* x   = (const float*)d_in[0];
    const int*   ei  = (const int*)d_in[1];
    const float* fw  = (const float*)d_in[2];
    const float* fb  = (const float*)d_in[3];
    const float* tri = (const float*)d_in[4];
    const float* mu  = (const float*)d_in[5];
    const float* sig = (const float*)d_in[6];
    const float* lw  = (const float*)d_in[7];
    const float* rc  = (const float*)d_in[8];
    const float* rr  = (const float*)d_in[9];
    const float* W   = (const float*)d_in[10];
    const float* ob  = (const float*)d_in[11];
    float* out = (float*)d_out;

    int loPri = 0, hiPri = 0;
    cudaDeviceGetStreamPriorityRange(&loPri, &hiPri);
    cudaStream_t s1;
    cudaStreamCreateWithPriority(&s1, cudaStreamNonBlocking, hiPri);
    cudaEvent_t evRoot, evT;
    cudaEventCreateWithFlags(&evRoot, cudaEventDisableTiming);
    cudaEventCreateWithFlags(&evT, cudaEventDisableTiming);

    cudaEventRecord(evRoot, 0);
    cudaStreamWaitEvent(s1, evRoot, 0);

    // x-GEMM (tensor cores) on default stream
    dim3 ggx((N_ + 127) / 128, FOUT / 64);
    k_gemm_x<<<ggx, 256>>>(x, W, ob, out);

    // topology pipeline on s1
    k_init<<<(KF * MS + 255) / 256, 256, 0, s1>>>();
    k_fall<<<(N_ + 7) / 8, 256, 0, s1>>>(x, fw, fb);

    for (int r = 0; r < 15; r++) {
        kA_edge<<<KF * E_ / 256, 256, 0, s1>>>(ei, r);
        kB_hook<<<KF * N_ / 256, 256, 0, s1>>>(ei, r);
        kC_flat<<<(KF * N_ + 255) / 256, 256, 0, s1>>>(r);
    }

    k_sloc<<<KF * (MS / 2048), 1024, 0, s1>>>();
    for (unsigned K2 = 4096; K2 <= MS; K2 <<= 1) {
        for (unsigned j = K2 >> 1; j >= 2048; j >>= 1)
            k_sglob<<<(KF * (MS / 2) + 255) / 256, 256, 0, s1>>>(K2, j);
        k_smerge<<<KF * (MS / 2048), 1024, 0, s1>>>(K2);
    }

    cudaFuncSetAttribute(k_uf, cudaFuncAttributeMaxDynamicSharedMemorySize, 122880);
    k_uf<<<KF, 32, 120000, s1>>>(ei);
    k_act<<<(N_ * KF + 255) / 256, 256, 0, s1>>>(tri, mu, sig, lw, rc, rr);
    cudaEventRecord(evT, s1);

    cudaStreamWaitEvent(0, evT, 0);
    dim3 ggc((N_ + 127) / 128, FOUT / 128);
    k_gemm_c<<<ggc, 256>>>(W, out);
}